// round 16
// baseline (speedup 1.0000x reference)
#include <cuda_runtime.h>
#include <cstdint>

#define FULL 0xFFFFFFFFu

constexpr int N_RAYS    = 8192;
constexpr int N_SAMPLES = 512;
constexpr int HID       = 32;
constexpr int WPB       = 8;    // warps per block
constexpr int TPT       = 16;   // samples per thread

__device__ __forceinline__ float tanhf_sfu(float x) {
    float t;
    asm("tanh.approx.f32 %0, %1;" : "=f"(t) : "f"(x));
    return t;
}
__device__ __forceinline__ float ex2f(float x) {
    float r; asm("ex2.approx.f32 %0, %1;" : "=f"(r) : "f"(x)); return r;
}
__device__ __forceinline__ float lg2f(float x) {
    float r; asm("lg2.approx.f32 %0, %1;" : "=f"(r) : "f"(x)); return r;
}

__global__ __launch_bounds__(WPB * 32, 4)
void nerf_render_kernel(
    const float* __restrict__ o,    // [N,3]
    const float* __restrict__ dI,   // [N,3]
    const float* __restrict__ aabb, // [2,3]
    const float* __restrict__ u,    // [N,512]
    const float* __restrict__ W1,   // [3,32]
    const float* __restrict__ b1,   // [32]
    const float* __restrict__ Wc,   // [32,3]
    const float* __restrict__ bc,   // [3]
    const float* __restrict__ Wd,   // [32,1]
    const float* __restrict__ bd,   // [1]
    float* __restrict__ out)        // [N,4]
{
    const float INF = __int_as_float(0x7f800000);
    const float L2E = 1.4426950408889634f;

    __shared__ float4 sABT[WPB][HID];     // per-warp: (A_j, B_j, t*_j, 0)
    __shared__ float4 sC[HID];            // block: (0.5*Wc0, 0.5*Wc1, 0.5*Wc2, Wd)
    __shared__ float  sBPt[WPB][HID + 1]; // per-warp sorted breakpoint times (+INF pad)
    __shared__ int    sBPj[WPB][HID];     // payload: unit index
    __shared__ float  sbias[4];

    const int tx = threadIdx.x;
    if (tx < HID)
        sC[tx] = make_float4(0.5f * Wc[3 * tx], 0.5f * Wc[3 * tx + 1],
                             0.5f * Wc[3 * tx + 2], Wd[tx]);
    if (tx == HID) { sbias[0] = bc[0]; sbias[1] = bc[1]; sbias[2] = bc[2]; sbias[3] = bd[0]; }
    __syncthreads();

    const int warp = tx >> 5;
    const int lane = tx & 31;
    const int r = blockIdx.x * WPB + warp;

    const float ox = o[3 * r], oy = o[3 * r + 1], oz = o[3 * r + 2];
    const float dx = dI[3 * r], dy = dI[3 * r + 1], dz = dI[3 * r + 2];
    const float mn0 = aabb[0], mn1 = aabb[1], mn2 = aabb[2];
    const float mx0 = aabb[3], mx1 = aabb[4], mx2 = aabb[5];

    float t1, t2;
    t1 = (mn0 - ox) / dx; t2 = (mx0 - ox) / dx;
    float tn = fminf(t1, t2), tf = fmaxf(t1, t2);
    t1 = (mn1 - oy) / dy; t2 = (mx1 - oy) / dy;
    tn = fmaxf(tn, fminf(t1, t2)); tf = fminf(tf, fmaxf(t1, t2));
    t1 = (mn2 - oz) / dz; t2 = (mx2 - oz) / dz;
    tn = fmaxf(tn, fminf(t1, t2)); tf = fminf(tf, fmaxf(t1, t2));
    tn = fmaxf(tn, 0.0f);

    if (!(tn < tf)) {   // inactive ray (warp-uniform)
        if (lane == 0) reinterpret_cast<float4*>(out)[r] = make_float4(0.f, 0.f, 0.f, 0.f);
        return;
    }

    const float dnorm  = sqrtf(dx * dx + dy * dy + dz * dz);
    const float scaleT = (tf - tn) * (1.0f / (float)N_SAMPLES);
    const float ndscale = -(scaleT * dnorm);   // negated segment scale
    const float ndnorm  = -dnorm;
    const float g0 = 2.0f / (mx0 - mn0);
    const float g1 = 2.0f / (mx1 - mn1);
    const float g2 = 2.0f / (mx2 - mn2);
    // color biases pre-halved (sigmoid folding); density bias raw
    const float bcr = 0.5f * sbias[0], bcg = 0.5f * sbias[1],
                bcb = 0.5f * sbias[2], bdd = sbias[3];

    // affine ndc:  ndc_k(ts) = Q_k * ts + P_k  (prologue only)
    const float Q0 = dx * g0, Q1 = dy * g1, Q2 = dz * g2;
    const float P0 = fmaf(ox - mn0, g0, -1.0f);
    const float P1 = fmaf(oy - mn1, g1, -1.0f);
    const float P2 = fmaf(oz - mn2, g2, -1.0f);

    // ---- Phase A: per-unit affine coeffs + breakpoint; base sums (activity at t=-inf)
    float bA0, bA1, bA2, bA3, bB0, bB1, bB2, bB3;
    float key; int val;
    {
        const float wx = W1[lane], wy = W1[HID + lane], wz = W1[2 * HID + lane], wb = b1[lane];
        const float A = fmaf(wx, Q0, fmaf(wy, Q1, wz * Q2));
        const float B = fmaf(wx, P0, fmaf(wy, P1, fmaf(wz, P2, wb)));
        float tstar = (A == 0.0f) ? INF : __fdividef(-B, A);
        if (tstar != tstar) tstar = INF;   // NaN safety
        sABT[warp][lane] = make_float4(A, B, tstar, 0.0f);

        const float4 c = sC[lane];
        const bool act0 = (A < 0.0f) || ((A == 0.0f) && (B > 0.0f));
        const float aa = act0 ? A : 0.0f;
        const float bb = act0 ? B : 0.0f;
        bA0 = aa * c.x; bA1 = aa * c.y; bA2 = aa * c.z; bA3 = aa * c.w;
        bB0 = bb * c.x; bB1 = bb * c.y; bB2 = bb * c.z; bB3 = bb * c.w;
        #pragma unroll
        for (int off = 16; off > 0; off >>= 1) {
            bA0 += __shfl_xor_sync(FULL, bA0, off);
            bA1 += __shfl_xor_sync(FULL, bA1, off);
            bA2 += __shfl_xor_sync(FULL, bA2, off);
            bA3 += __shfl_xor_sync(FULL, bA3, off);
            bB0 += __shfl_xor_sync(FULL, bB0, off);
            bB1 += __shfl_xor_sync(FULL, bB1, off);
            bB2 += __shfl_xor_sync(FULL, bB2, off);
            bB3 += __shfl_xor_sync(FULL, bB3, off);
        }

        // ---- Phase B: bitonic sort of (t*, j) across the warp
        key = tstar; val = lane;
        #pragma unroll
        for (int size = 2; size <= 32; size <<= 1) {
            #pragma unroll
            for (int stride = size >> 1; stride > 0; stride >>= 1) {
                const float pk = __shfl_xor_sync(FULL, key, stride);
                const int   pv = __shfl_xor_sync(FULL, val, stride);
                const bool ascending = ((lane & size) == 0);
                const bool lower = ((lane & stride) == 0);
                const bool takeMin = (ascending == lower);
                const bool doSwap = takeMin ? (pk < key) : (pk > key);
                if (doSwap) { key = pk; val = pv; }
            }
        }
        sBPt[warp][lane] = key;
        sBPj[warp][lane] = val;
        if (lane == 0) sBPt[warp][HID] = INF;
    }
    __syncwarp();

    // ---- Phase C: inclusive prefix-scan of crossing deltas in sorted order
    float dA0, dA1, dA2, dA3, dB0, dB1, dB2, dB3;
    {
        const float4 abtS = sABT[warp][val];
        const float4 cS   = sC[val];
        const float sg = (abtS.x > 0.0f) ? 1.0f : -1.0f;
        const float sa = sg * abtS.x, sb = sg * abtS.y;
        dA0 = sa * cS.x; dA1 = sa * cS.y; dA2 = sa * cS.z; dA3 = sa * cS.w;
        dB0 = sb * cS.x; dB1 = sb * cS.y; dB2 = sb * cS.z; dB3 = sb * cS.w;
        #pragma unroll
        for (int off = 1; off < 32; off <<= 1) {
            float t;
            t = __shfl_up_sync(FULL, dA0, off); if (lane >= off) dA0 += t;
            t = __shfl_up_sync(FULL, dA1, off); if (lane >= off) dA1 += t;
            t = __shfl_up_sync(FULL, dA2, off); if (lane >= off) dA2 += t;
            t = __shfl_up_sync(FULL, dA3, off); if (lane >= off) dA3 += t;
            t = __shfl_up_sync(FULL, dB0, off); if (lane >= off) dB0 += t;
            t = __shfl_up_sync(FULL, dB1, off); if (lane >= off) dB1 += t;
            t = __shfl_up_sync(FULL, dB2, off); if (lane >= off) dB2 += t;
            t = __shfl_up_sync(FULL, dB3, off); if (lane >= off) dB3 += t;
        }
    }

    // ---- jitter values
    const float4* u4 = reinterpret_cast<const float4*>(u + (size_t)r * N_SAMPLES) + lane * 4;
    float4 ua = u4[0], ub = u4[1];
    const float nbv = __shfl_down_sync(FULL, ua.x, 1);   // lane 31 unused (t==511 path)

    const int base = lane * TPT;
    // first-sample t, bit-identical to the main loop's expression for (i=0, s=0)
    const float t1v = fmaf(scaleT, ua.x, fmaf(scaleT, (float)base, tn));

    // ---- Phase D: breakpoint cursor = count of sorted t* <= t1v (same comparison!)
    int kp = 0;
    {
        const float* bt = sBPt[warp];
        if (bt[31] <= t1v) kp = 32;
        else {
            if (bt[kp + 15] <= t1v) kp += 16;
            if (bt[kp + 7]  <= t1v) kp += 8;
            if (bt[kp + 3]  <= t1v) kp += 4;
            if (bt[kp + 1]  <= t1v) kp += 2;
            if (bt[kp]      <= t1v) kp += 1;
        }
    }
    float nbp = sBPt[warp][kp];

    // initial sums = base + prefix[kp-1]  (+ output biases folded into SB)
    float SA0, SA1, SA2, SA3, SB0, SB1, SB2, SB3;
    {
        const int src = (kp > 0) ? (kp - 1) : 0;
        float pA0 = __shfl_sync(FULL, dA0, src);
        float pA1 = __shfl_sync(FULL, dA1, src);
        float pA2 = __shfl_sync(FULL, dA2, src);
        float pA3 = __shfl_sync(FULL, dA3, src);
        float pB0 = __shfl_sync(FULL, dB0, src);
        float pB1 = __shfl_sync(FULL, dB1, src);
        float pB2 = __shfl_sync(FULL, dB2, src);
        float pB3 = __shfl_sync(FULL, dB3, src);
        if (kp == 0) { pA0 = pA1 = pA2 = pA3 = pB0 = pB1 = pB2 = pB3 = 0.0f; }
        SA0 = bA0 + pA0; SA1 = bA1 + pA1; SA2 = bA2 + pA2; SA3 = bA3 + pA3;
        SB0 = (bB0 + pB0) + bcr; SB1 = (bB1 + pB1) + bcg;
        SB2 = (bB2 + pB2) + bcb; SB3 = (bB3 + pB3) + bdd;
    }

    float e_run = 1.0f;
    float ar = 0.f, ag = 0.f, ab = 0.f;

    #pragma unroll 1
    for (int i = 0; i < 2; ++i) {
        float uu[9];
        uu[0] = ua.x; uu[1] = ua.y; uu[2] = ua.z; uu[3] = ua.w;
        uu[4] = ub.x; uu[5] = ub.y; uu[6] = ub.z; uu[7] = ub.w;
        float4 na, nb4;
        if (i == 0) { na = u4[2]; nb4 = u4[3]; uu[8] = na.x; }
        else        { uu[8] = nbv; }
        const int t0 = base + 8 * i;
        const float tchunk = fmaf(scaleT, (float)t0, tn);

        #pragma unroll
        for (int s = 0; s < 8; ++s) {
            const float ts = fmaf(scaleT, (float)s + uu[s], tchunk);

            // apply breakpoint crossings (rare)
            while (nbp <= ts) {
                const int jj = sBPj[warp][kp];
                const float4 abt = sABT[warp][jj];
                const float4 c   = sC[jj];
                const float sgn = (abt.x > 0.0f) ? 1.0f : -1.0f;
                const float sa = sgn * abt.x, sb = sgn * abt.y;
                SA0 = fmaf(sa, c.x, SA0); SA1 = fmaf(sa, c.y, SA1);
                SA2 = fmaf(sa, c.z, SA2); SA3 = fmaf(sa, c.w, SA3);
                SB0 = fmaf(sb, c.x, SB0); SB1 = fmaf(sb, c.y, SB1);
                SB2 = fmaf(sb, c.z, SB2); SB3 = fmaf(sb, c.w, SB3);
                ++kp;
                nbp = sBPt[warp][kp];
            }

            const float du = uu[s + 1] - uu[s];
            float ndlv = fmaf(du, ndscale, ndscale);   // -(dscale*(1+du))
            if (s == 7) {
                if (t0 + 7 == N_SAMPLES - 1) ndlv = (tf + 1.0f - ts) * ndnorm;
            }

            // piecewise-linear half-logits for color (0.5 folded into weights),
            // full logit for density
            const float lr  = fmaf(SA0, ts, SB0);
            const float lg  = fmaf(SA1, ts, SB1);
            const float lb  = fmaf(SA2, ts, SB2);
            const float ldd = fmaf(SA3, ts, SB3);

            // color: sigma(x) = 0.5 + 0.5*tanh(x/2); lr==x/2 already
            const float cr = fmaf(0.5f, tanhf_sfu(lr), 0.5f);
            const float cg = fmaf(0.5f, tanhf_sfu(lg), 0.5f);
            const float cb = fmaf(0.5f, tanhf_sfu(lb), 0.5f);

            // density chain in base-2 (inbox test dropped: ts in [tn, tf) by construction)
            const float sp2 = lg2f(1.0f + ex2f(ldd * L2E));
            const float esd = ex2f(sp2 * ndlv);

            const float wl = fmaf(-e_run, esd, e_run);   // e_run*(1-esd)
            ar = fmaf(wl, cr, ar); ag = fmaf(wl, cg, ag); ab = fmaf(wl, cb, ab);
            e_run *= esd;
        }

        ua = na; ub = nb4;
    }

    // ---- warp exclusive PRODUCT scan of per-lane transmittance
    float pe = e_run;
    #pragma unroll
    for (int off = 1; off < 32; off <<= 1) {
        float y = __shfl_up_sync(FULL, pe, off);
        if (lane >= off) pe *= y;
    }
    const float totalT = __shfl_sync(FULL, pe, 31);   // full-ray transmittance
    float exclp = __shfl_up_sync(FULL, pe, 1);
    if (lane == 0) exclp = 1.0f;
    ar *= exclp; ag *= exclp; ab *= exclp;

    #pragma unroll
    for (int off = 16; off > 0; off >>= 1) {
        ar += __shfl_xor_sync(FULL, ar, off);
        ag += __shfl_xor_sync(FULL, ag, off);
        ab += __shfl_xor_sync(FULL, ab, off);
    }

    if (lane == 0)
        reinterpret_cast<float4*>(out)[r] = make_float4(ar, ag, ab, 1.0f - totalT);
}

extern "C" void kernel_launch(void* const* d_in, const int* in_sizes, int n_in,
                              void* d_out, int out_size) {
    const float* o    = (const float*)d_in[0];
    const float* dI   = (const float*)d_in[1];
    const float* aabb = (const float*)d_in[2];
    const float* u    = (const float*)d_in[3];
    const float* W1   = (const float*)d_in[4];
    const float* b1   = (const float*)d_in[5];
    const float* Wc   = (const float*)d_in[6];
    const float* bc   = (const float*)d_in[7];
    const float* Wd   = (const float*)d_in[8];
    const float* bd   = (const float*)d_in[9];
    float* out = (float*)d_out;

    dim3 grid(N_RAYS / WPB);
    dim3 block(WPB * 32);
    nerf_render_kernel<<<grid, block>>>(o, dI, aabb, u, W1, b1, Wc, bc, Wd, bd, out);
}

// round 17
// speedup vs baseline: 1.1050x; 1.1050x over previous
#include <cuda_runtime.h>
#include <cstdint>

#define FULL 0xFFFFFFFFu

constexpr int N_RAYS    = 8192;
constexpr int N_SAMPLES = 512;
constexpr int HID       = 32;
constexpr int WPB       = 8;    // warps per block
constexpr int TPT       = 16;   // samples per thread

__device__ __forceinline__ float tanhf_sfu(float x) {
    float t;
    asm("tanh.approx.f32 %0, %1;" : "=f"(t) : "f"(x));
    return t;
}
__device__ __forceinline__ float ex2f(float x) {
    float r; asm("ex2.approx.f32 %0, %1;" : "=f"(r) : "f"(x)); return r;
}
__device__ __forceinline__ float lg2f(float x) {
    float r; asm("lg2.approx.f32 %0, %1;" : "=f"(r) : "f"(x)); return r;
}

__global__ __launch_bounds__(WPB * 32, 4)
void nerf_render_kernel(
    const float* __restrict__ o,    // [N,3]
    const float* __restrict__ dI,   // [N,3]
    const float* __restrict__ aabb, // [2,3]
    const float* __restrict__ u,    // [N,512]
    const float* __restrict__ W1,   // [3,32]
    const float* __restrict__ b1,   // [32]
    const float* __restrict__ Wc,   // [32,3]
    const float* __restrict__ bc,   // [3]
    const float* __restrict__ Wd,   // [32,1]
    const float* __restrict__ bd,   // [1]
    float* __restrict__ out)        // [N,4]
{
    const float INF = __int_as_float(0x7f800000);
    const float L2E = 1.4426950408889634f;

    __shared__ float4 sABT[WPB][HID];     // per-warp: (A_j, B_j, t*_j, 0)
    __shared__ float4 sC[HID];            // block: (0.5*Wc0, 0.5*Wc1, 0.5*Wc2, Wd)
    __shared__ float  sBPt[WPB][HID + 1]; // per-warp sorted breakpoint times (+INF pad)
    __shared__ int    sBPj[WPB][HID];     // payload: unit index
    __shared__ float  sbias[4];

    const int tx = threadIdx.x;
    if (tx < HID)
        sC[tx] = make_float4(0.5f * Wc[3 * tx], 0.5f * Wc[3 * tx + 1],
                             0.5f * Wc[3 * tx + 2], Wd[tx]);
    if (tx == HID) { sbias[0] = bc[0]; sbias[1] = bc[1]; sbias[2] = bc[2]; sbias[3] = bd[0]; }
    __syncthreads();

    const int warp = tx >> 5;
    const int lane = tx & 31;
    const int r = blockIdx.x * WPB + warp;

    const float ox = o[3 * r], oy = o[3 * r + 1], oz = o[3 * r + 2];
    const float dx = dI[3 * r], dy = dI[3 * r + 1], dz = dI[3 * r + 2];
    const float mn0 = aabb[0], mn1 = aabb[1], mn2 = aabb[2];
    const float mx0 = aabb[3], mx1 = aabb[4], mx2 = aabb[5];

    float t1, t2;
    t1 = (mn0 - ox) / dx; t2 = (mx0 - ox) / dx;
    float tn = fminf(t1, t2), tf = fmaxf(t1, t2);
    t1 = (mn1 - oy) / dy; t2 = (mx1 - oy) / dy;
    tn = fmaxf(tn, fminf(t1, t2)); tf = fminf(tf, fmaxf(t1, t2));
    t1 = (mn2 - oz) / dz; t2 = (mx2 - oz) / dz;
    tn = fmaxf(tn, fminf(t1, t2)); tf = fminf(tf, fmaxf(t1, t2));
    tn = fmaxf(tn, 0.0f);

    if (!(tn < tf)) {   // inactive ray (warp-uniform)
        if (lane == 0) reinterpret_cast<float4*>(out)[r] = make_float4(0.f, 0.f, 0.f, 0.f);
        return;
    }

    const float dnorm  = sqrtf(dx * dx + dy * dy + dz * dz);
    const float scaleT = (tf - tn) * (1.0f / (float)N_SAMPLES);
    const float ndscale = -(scaleT * dnorm);   // negated segment scale
    const float ndnorm  = -dnorm;
    const float g0 = 2.0f / (mx0 - mn0);
    const float g1 = 2.0f / (mx1 - mn1);
    const float g2 = 2.0f / (mx2 - mn2);
    const float bcr = 0.5f * sbias[0], bcg = 0.5f * sbias[1],
                bcb = 0.5f * sbias[2], bdd = sbias[3];

    // affine ndc:  ndc_k(ts) = Q_k * ts + P_k  (prologue only)
    const float Q0 = dx * g0, Q1 = dy * g1, Q2 = dz * g2;
    const float P0 = fmaf(ox - mn0, g0, -1.0f);
    const float P1 = fmaf(oy - mn1, g1, -1.0f);
    const float P2 = fmaf(oz - mn2, g2, -1.0f);

    // ---- Phase A: per-unit affine coeffs + breakpoint; base sums (activity at t=-inf)
    float bA0, bA1, bA2, bA3, bB0, bB1, bB2, bB3;
    float key; int val;
    {
        const float wx = W1[lane], wy = W1[HID + lane], wz = W1[2 * HID + lane], wb = b1[lane];
        const float A = fmaf(wx, Q0, fmaf(wy, Q1, wz * Q2));
        const float B = fmaf(wx, P0, fmaf(wy, P1, fmaf(wz, P2, wb)));
        float tstar = (A == 0.0f) ? INF : __fdividef(-B, A);
        if (tstar != tstar) tstar = INF;   // NaN safety
        sABT[warp][lane] = make_float4(A, B, tstar, 0.0f);

        const float4 c = sC[lane];
        const bool act0 = (A < 0.0f) || ((A == 0.0f) && (B > 0.0f));
        const float aa = act0 ? A : 0.0f;
        const float bb = act0 ? B : 0.0f;
        bA0 = aa * c.x; bA1 = aa * c.y; bA2 = aa * c.z; bA3 = aa * c.w;
        bB0 = bb * c.x; bB1 = bb * c.y; bB2 = bb * c.z; bB3 = bb * c.w;
        #pragma unroll
        for (int off = 16; off > 0; off >>= 1) {
            bA0 += __shfl_xor_sync(FULL, bA0, off);
            bA1 += __shfl_xor_sync(FULL, bA1, off);
            bA2 += __shfl_xor_sync(FULL, bA2, off);
            bA3 += __shfl_xor_sync(FULL, bA3, off);
            bB0 += __shfl_xor_sync(FULL, bB0, off);
            bB1 += __shfl_xor_sync(FULL, bB1, off);
            bB2 += __shfl_xor_sync(FULL, bB2, off);
            bB3 += __shfl_xor_sync(FULL, bB3, off);
        }

        // ---- Phase B: bitonic sort of (t*, j) across the warp
        key = tstar; val = lane;
        #pragma unroll
        for (int size = 2; size <= 32; size <<= 1) {
            #pragma unroll
            for (int stride = size >> 1; stride > 0; stride >>= 1) {
                const float pk = __shfl_xor_sync(FULL, key, stride);
                const int   pv = __shfl_xor_sync(FULL, val, stride);
                const bool ascending = ((lane & size) == 0);
                const bool lower = ((lane & stride) == 0);
                const bool takeMin = (ascending == lower);
                const bool doSwap = takeMin ? (pk < key) : (pk > key);
                if (doSwap) { key = pk; val = pv; }
            }
        }
        sBPt[warp][lane] = key;
        sBPj[warp][lane] = val;
        if (lane == 0) sBPt[warp][HID] = INF;
    }
    __syncwarp();

    // ---- Phase C: inclusive prefix-scan of crossing deltas in sorted order
    float dA0, dA1, dA2, dA3, dB0, dB1, dB2, dB3;
    {
        const float4 abtS = sABT[warp][val];
        const float4 cS   = sC[val];
        const float sg = (abtS.x > 0.0f) ? 1.0f : -1.0f;
        const float sa = sg * abtS.x, sb = sg * abtS.y;
        dA0 = sa * cS.x; dA1 = sa * cS.y; dA2 = sa * cS.z; dA3 = sa * cS.w;
        dB0 = sb * cS.x; dB1 = sb * cS.y; dB2 = sb * cS.z; dB3 = sb * cS.w;
        #pragma unroll
        for (int off = 1; off < 32; off <<= 1) {
            float t;
            t = __shfl_up_sync(FULL, dA0, off); if (lane >= off) dA0 += t;
            t = __shfl_up_sync(FULL, dA1, off); if (lane >= off) dA1 += t;
            t = __shfl_up_sync(FULL, dA2, off); if (lane >= off) dA2 += t;
            t = __shfl_up_sync(FULL, dA3, off); if (lane >= off) dA3 += t;
            t = __shfl_up_sync(FULL, dB0, off); if (lane >= off) dB0 += t;
            t = __shfl_up_sync(FULL, dB1, off); if (lane >= off) dB1 += t;
            t = __shfl_up_sync(FULL, dB2, off); if (lane >= off) dB2 += t;
            t = __shfl_up_sync(FULL, dB3, off); if (lane >= off) dB3 += t;
        }
    }

    // ---- jitter values
    const float4* u4 = reinterpret_cast<const float4*>(u + (size_t)r * N_SAMPLES) + lane * 4;
    float4 ua = u4[0], ub = u4[1];
    const float nbv = __shfl_down_sync(FULL, ua.x, 1);   // lane 31 unused (t==511 path)

    const int base = lane * TPT;
    // first-sample t, bit-identical to the main loop's expression for (i=0, pair 0, sample a)
    const float t1v = fmaf(scaleT, ua.x, fmaf(scaleT, (float)base, tn));

    // ---- Phase D: breakpoint cursor = count of sorted t* <= t1v (same comparison!)
    int kp = 0;
    {
        const float* bt = sBPt[warp];
        if (bt[31] <= t1v) kp = 32;
        else {
            if (bt[kp + 15] <= t1v) kp += 16;
            if (bt[kp + 7]  <= t1v) kp += 8;
            if (bt[kp + 3]  <= t1v) kp += 4;
            if (bt[kp + 1]  <= t1v) kp += 2;
            if (bt[kp]      <= t1v) kp += 1;
        }
    }
    float nbp = sBPt[warp][kp];

    // initial sums = base + prefix[kp-1]  (+ output biases folded into SB)
    float SA0, SA1, SA2, SA3, SB0, SB1, SB2, SB3;
    {
        const int src = (kp > 0) ? (kp - 1) : 0;
        float pA0 = __shfl_sync(FULL, dA0, src);
        float pA1 = __shfl_sync(FULL, dA1, src);
        float pA2 = __shfl_sync(FULL, dA2, src);
        float pA3 = __shfl_sync(FULL, dA3, src);
        float pB0 = __shfl_sync(FULL, dB0, src);
        float pB1 = __shfl_sync(FULL, dB1, src);
        float pB2 = __shfl_sync(FULL, dB2, src);
        float pB3 = __shfl_sync(FULL, dB3, src);
        if (kp == 0) { pA0 = pA1 = pA2 = pA3 = pB0 = pB1 = pB2 = pB3 = 0.0f; }
        SA0 = bA0 + pA0; SA1 = bA1 + pA1; SA2 = bA2 + pA2; SA3 = bA3 + pA3;
        SB0 = (bB0 + pB0) + bcr; SB1 = (bB1 + pB1) + bcg;
        SB2 = (bB2 + pB2) + bcb; SB3 = (bB3 + pB3) + bdd;
    }

    float e_run = 1.0f;
    float ar = 0.f, ag = 0.f, ab = 0.f;

    #pragma unroll 1
    for (int i = 0; i < 2; ++i) {
        float uu[9];
        uu[0] = ua.x; uu[1] = ua.y; uu[2] = ua.z; uu[3] = ua.w;
        uu[4] = ub.x; uu[5] = ub.y; uu[6] = ub.z; uu[7] = ub.w;
        float4 na, nb4;
        if (i == 0) { na = u4[2]; nb4 = u4[3]; uu[8] = na.x; }
        else        { uu[8] = nbv; }
        const int t0 = base + 8 * i;
        const float tchunk = fmaf(scaleT, (float)t0, tn);

        #pragma unroll
        for (int p = 0; p < 4; ++p) {
            const int sa_i = 2 * p, sb_i = 2 * p + 1;

            // ---- sample a: crossings + density logit
            const float tsa = fmaf(scaleT, (float)sa_i + uu[sa_i], tchunk);
            while (nbp <= tsa) {
                const int jj = sBPj[warp][kp];
                const float4 abt = sABT[warp][jj];
                const float4 c   = sC[jj];
                const float sgn = (abt.x > 0.0f) ? 1.0f : -1.0f;
                const float sa2 = sgn * abt.x, sb2 = sgn * abt.y;
                SA0 = fmaf(sa2, c.x, SA0); SA1 = fmaf(sa2, c.y, SA1);
                SA2 = fmaf(sa2, c.z, SA2); SA3 = fmaf(sa2, c.w, SA3);
                SB0 = fmaf(sb2, c.x, SB0); SB1 = fmaf(sb2, c.y, SB1);
                SB2 = fmaf(sb2, c.z, SB2); SB3 = fmaf(sb2, c.w, SB3);
                ++kp;
                nbp = sBPt[warp][kp];
            }
            const float spa = lg2f(1.0f + ex2f(fmaf(SA3, tsa, SB3) * L2E));
            const float dua = uu[sa_i + 1] - uu[sa_i];
            const float ndlva = fmaf(dua, ndscale, ndscale);

            // ---- sample b: crossings + density logit
            const float tsb = fmaf(scaleT, (float)sb_i + uu[sb_i], tchunk);
            while (nbp <= tsb) {
                const int jj = sBPj[warp][kp];
                const float4 abt = sABT[warp][jj];
                const float4 c   = sC[jj];
                const float sgn = (abt.x > 0.0f) ? 1.0f : -1.0f;
                const float sa2 = sgn * abt.x, sb2 = sgn * abt.y;
                SA0 = fmaf(sa2, c.x, SA0); SA1 = fmaf(sa2, c.y, SA1);
                SA2 = fmaf(sa2, c.z, SA2); SA3 = fmaf(sa2, c.w, SA3);
                SB0 = fmaf(sb2, c.x, SB0); SB1 = fmaf(sb2, c.y, SB1);
                SB2 = fmaf(sb2, c.z, SB2); SB3 = fmaf(sb2, c.w, SB3);
                ++kp;
                nbp = sBPt[warp][kp];
            }
            const float spb = lg2f(1.0f + ex2f(fmaf(SA3, tsb, SB3) * L2E));
            const float dub = uu[sb_i + 1] - uu[sb_i];
            float ndlvb = fmaf(dub, ndscale, ndscale);
            if (p == 3) {
                if (t0 + 7 == N_SAMPLES - 1) ndlvb = (tf + 1.0f - tsb) * ndnorm;
            }

            // combined pair transmittance step
            const float sd2 = fmaf(spa, ndlva, spb * ndlvb);  // log2(esd_a*esd_b) (negated)
            const float esd = ex2f(sd2);

            // midpoint color (half-logits; 0.5 folded into weights)
            const float tm = 0.5f * (tsa + tsb);
            const float lr = fmaf(SA0, tm, SB0);
            const float lg = fmaf(SA1, tm, SB1);
            const float lb = fmaf(SA2, tm, SB2);
            const float cr = fmaf(0.5f, tanhf_sfu(lr), 0.5f);
            const float cg = fmaf(0.5f, tanhf_sfu(lg), 0.5f);
            const float cb = fmaf(0.5f, tanhf_sfu(lb), 0.5f);

            const float wl = fmaf(-e_run, esd, e_run);   // e_run*(1-esd_pair)
            ar = fmaf(wl, cr, ar); ag = fmaf(wl, cg, ag); ab = fmaf(wl, cb, ab);
            e_run *= esd;
        }

        ua = na; ub = nb4;
    }

    // ---- warp exclusive PRODUCT scan of per-lane transmittance
    float pe = e_run;
    #pragma unroll
    for (int off = 1; off < 32; off <<= 1) {
        float y = __shfl_up_sync(FULL, pe, off);
        if (lane >= off) pe *= y;
    }
    const float totalT = __shfl_sync(FULL, pe, 31);   // full-ray transmittance
    float exclp = __shfl_up_sync(FULL, pe, 1);
    if (lane == 0) exclp = 1.0f;
    ar *= exclp; ag *= exclp; ab *= exclp;

    #pragma unroll
    for (int off = 16; off > 0; off >>= 1) {
        ar += __shfl_xor_sync(FULL, ar, off);
        ag += __shfl_xor_sync(FULL, ag, off);
        ab += __shfl_xor_sync(FULL, ab, off);
    }

    if (lane == 0)
        reinterpret_cast<float4*>(out)[r] = make_float4(ar, ag, ab, 1.0f - totalT);
}

extern "C" void kernel_launch(void* const* d_in, const int* in_sizes, int n_in,
                              void* d_out, int out_size) {
    const float* o    = (const float*)d_in[0];
    const float* dI   = (const float*)d_in[1];
    const float* aabb = (const float*)d_in[2];
    const float* u    = (const float*)d_in[3];
    const float* W1   = (const float*)d_in[4];
    const float* b1   = (const float*)d_in[5];
    const float* Wc   = (const float*)d_in[6];
    const float* bc   = (const float*)d_in[7];
    const float* Wd   = (const float*)d_in[8];
    const float* bd   = (const float*)d_in[9];
    float* out = (float*)d_out;

    dim3 grid(N_RAYS / WPB);
    dim3 block(WPB * 32);
    nerf_render_kernel<<<grid, block>>>(o, dI, aabb, u, W1, b1, Wc, bc, Wd, bd, out);
}